// round 6
// baseline (speedup 1.0000x reference)
#include <cuda_runtime.h>
#include <cstdint>
#include <math.h>

#define BB 256
#define TT 512
#define HH 256
#define EE 6
#define VV 10
#define CC 10

#define CLUSTER 8
#define NB 16            // batch columns per cluster
#define ROWS 32          // h-rows per CTA
#define SR 128           // stacked gate rows per CTA (4 gates * 32)
#define THREADS 1024     // 32 warps: sr(128) x kq(4) x column-half(2)
#define KQ 4

#define SRP 132          // padded sr dimension (128 used)
#define KPP 132          // padded kp dimension (128 used)

typedef unsigned long long ull;

struct __align__(16) Smem {
    float Wp4[64][128][4];       // [k>>2][sr][k&3] = Wh_gate[rowBase+lr][k]   (131072 B)
    float Hp[2][NB][KPP][2];     // [buf][col][kp][par] = h[2kp+par][col]      (33792 B)
    float Pre[KQ][NB][SRP];      // [kq][col][sr] partial pre-activations      (33792 B)
    float Cc[NB][ROWS];          // [col][hr] c-state                           (2048 B)
    float Tab[VV][SRP];          // [digit][sr] = (Wx@emb^T)[sr][digit]         (5280 B)
    float Bias[4][NB];
    unsigned char dig8[NB][TT];  // all digits preloaded                        (8192 B)
};

#define FMA2(a, b, c) asm("fma.rn.f32x2 %0, %1, %2, %0;" : "+l"(a) : "l"(b), "l"(c))

__device__ __forceinline__ void cluster_sync_() {
    asm volatile("barrier.cluster.arrive.aligned;" ::: "memory");
    asm volatile("barrier.cluster.wait.aligned;" ::: "memory");
}

__device__ __forceinline__ float fast_sigmoid(float x) {
    return __fdividef(1.0f, 1.0f + __expf(-x));
}
__device__ __forceinline__ float fast_tanh(float x) {
    return 1.0f - __fdividef(2.0f, __expf(2.0f * x) + 1.0f);
}

__global__ void __cluster_dims__(CLUSTER, 1, 1) __launch_bounds__(THREADS, 1)
lstm_persistent_kernel(
    const int* __restrict__ x,   const float* __restrict__ emb,
    const float* __restrict__ Wxg, const float* __restrict__ Whg, const float* __restrict__ bg,
    const float* __restrict__ Wxi, const float* __restrict__ Whi, const float* __restrict__ bi,
    const float* __restrict__ Wxf, const float* __restrict__ Whf, const float* __restrict__ bf,
    const float* __restrict__ Wxo, const float* __restrict__ Who, const float* __restrict__ bo,
    const float* __restrict__ Wp,  const float* __restrict__ bp,
    float* __restrict__ out)
{
    extern __shared__ __align__(16) unsigned char smem_raw[];
    Smem& s = *reinterpret_cast<Smem*>(smem_raw);

    const int tid = threadIdx.x;
    uint32_t rank;
    asm("mov.u32 %0, %%cluster_ctarank;" : "=r"(rank));
    const int cluster = blockIdx.x / CLUSTER;
    const int colBase = cluster * NB;
    const int rowBase = (int)rank * ROWS;

    const float* WhArr[4] = {Whg, Whi, Whf, Who};
    const float* WxArr[4] = {Wxg, Wxi, Wxf, Wxo};
    const float* bArr[4]  = {bg,  bi,  bf,  bo};

    // ---------------- Prologue ----------------
    {
        const int warp = tid >> 5, lane = tid & 31;
        // k-quadded transposed weights: Wp4[k>>2][sr][k&3] = Wh_gate[rowBase+lr][k]
        for (int sr = warp; sr < SR; sr += 32) {
            const int gate = sr >> 5, lr = sr & 31;
            const float* src = WhArr[gate] + (size_t)(rowBase + lr) * HH;
            #pragma unroll
            for (int k = lane; k < HH; k += 32)
                s.Wp4[k >> 2][sr][k & 3] = src[k];
        }
    }
    // Gate digit tables (transposed): Tab[d][sr] = (Wx_gate @ emb^T)[row, d]
    for (int sr = tid; sr < SR; sr += THREADS) {
        const int gate = sr >> 5, lr = sr & 31;
        const float* wx = WxArr[gate] + (size_t)(rowBase + lr) * EE;
        #pragma unroll
        for (int d = 0; d < VV; d++) {
            float acc = 0.0f;
            #pragma unroll
            for (int e = 0; e < EE; e++) acc += wx[e] * emb[d * EE + e];
            s.Tab[d][sr] = acc;
        }
    }
    // Reference semantics: (H,B) + (H,) broadcasts over trailing (batch) axis
    // since H==B, so bias is indexed by BATCH column.
    if (tid < 4 * NB) {
        const int gate = tid / NB, c = tid % NB;
        s.Bias[gate][c] = bArr[gate][colBase + c];
    }
    // Zero h (both buffers) and c
    for (int i = tid; i < 2 * NB * KPP * 2; i += THREADS)
        reinterpret_cast<float*>(s.Hp)[i] = 0.0f;
    for (int i = tid; i < NB * ROWS; i += THREADS)
        reinterpret_cast<float*>(s.Cc)[i] = 0.0f;
    // Preload ALL digits as u8 (no per-step global loads)
    for (int i = tid; i < NB * TT; i += THREADS) {
        const int col = i >> 9, t = i & (TT - 1);
        s.dig8[col][t] = (unsigned char)x[(size_t)(colBase + col) * TT + t];
    }

    __syncthreads();
    cluster_sync_();   // peers' Hp zeroed before any remote h writes

    const int sr = tid & (SR - 1);       // stacked gate row (GEMM phase)
    const int kq = (tid >> 7) & 3;       // k-quarter (0..3)
    const int chalf = tid >> 9;          // column half (0/1)
    const int cb = chalf * 8;            // first column of this thread's half

    const int hr = tid & 31;             // epilogue: own h row
    const int ec = (tid >> 5) & 15;      // epilogue: own column (0..15)

    // Precompute the 8 remote DSMEM base addresses (mapa once, not per step)
    uint32_t rbase[CLUSTER];
    {
        uint32_t l0 = (uint32_t)__cvta_generic_to_shared(&s.Hp[0][0][0][0]);
        #pragma unroll
        for (int r = 0; r < CLUSTER; r++)
            asm("mapa.shared::cluster.u32 %0, %1, %2;" : "=r"(rbase[r]) : "r"(l0), "r"(r));
    }
    // byte offset within Hp for this thread's h pair store (per buffer)
    const uint32_t pairOff = (uint32_t)(ec * (KPP * 2 * 4) + ((int)rank * 16 + (hr >> 1)) * 8);
    const uint32_t bufStride = NB * KPP * 2 * 4;

    int cur = 0;

    for (int t = 0; t < TT; t++) {
        // ---- recurrent GEMM, k-paired f32x2: 8 columns per thread ----
        ull acc[8];
        #pragma unroll
        for (int c = 0; c < 8; c++) acc[c] = 0ULL;

        const ulonglong2* __restrict__ wq =
            reinterpret_cast<const ulonglong2*>(&s.Wp4[kq * 16][sr][0]);
        const float* __restrict__ hbase = &s.Hp[cur][cb][kq * 32][0];

        #pragma unroll 4
        for (int j = 0; j < 16; j++) {
            const ulonglong2 w = wq[(size_t)j * 128];      // Wp4[kq*16+j][sr][0..3]
            const float* hj = hbase + j * 4;               // kp = kq*32 + 2j
            #pragma unroll
            for (int c = 0; c < 8; c++) {
                const ulonglong2 h2 =
                    *reinterpret_cast<const ulonglong2*>(hj + c * (KPP * 2));
                FMA2(acc[c], w.x, h2.x);
                FMA2(acc[c], w.y, h2.y);
            }
        }
        // horizontal (even+odd) add, store partials lane-contiguously
        #pragma unroll
        for (int c = 0; c < 8; c++) {
            const float2 p = *reinterpret_cast<const float2*>(&acc[c]);
            s.Pre[kq][cb + c][sr] = p.x + p.y;
        }
        __syncthreads();

        // ---- epilogue: first 512 threads, one h value each ----
        if (tid < 512) {
            const int d = s.dig8[ec][t];
            float pre[4];
            #pragma unroll
            for (int g = 0; g < 4; g++) {
                const int gr = g * 32 + hr;
                pre[g] = s.Pre[0][ec][gr] + s.Pre[1][ec][gr]
                       + s.Pre[2][ec][gr] + s.Pre[3][ec][gr]
                       + s.Tab[d][gr] + s.Bias[g][ec];
            }
            const float gg = fast_tanh(pre[0]);
            const float ii = fast_sigmoid(pre[1]);
            const float ff = fast_sigmoid(pre[2]);
            const float oo = fast_sigmoid(pre[3]);
            const float cc = gg * ii + s.Cc[ec][hr] * ff;
            s.Cc[ec][hr] = cc;
            const float hh = fast_tanh(cc) * oo;

            // pair (even,odd) rows into one 8B value, broadcast to all 8 CTAs
            const int nxt = cur ^ 1;
            const float hhOdd = __shfl_down_sync(0xffffffffu, hh, 1);
            if ((hr & 1) == 0) {
                ull hp;
                asm("mov.b64 %0, {%1, %2};" : "=l"(hp) : "f"(hh), "f"(hhOdd));
                const uint32_t off = pairOff + (uint32_t)nxt * bufStride;
                #pragma unroll
                for (int r = 0; r < CLUSTER; r++) {
                    asm volatile("st.shared::cluster.b64 [%0], %1;"
                                 :: "r"(rbase[r] + off), "l"(hp) : "memory");
                }
            }
        }

        cluster_sync_();   // remote h writes visible cluster-wide
        cur ^= 1;
    }

    // -------- Final projection: out[b][j] = Wp[j,:] . h[:,b] + bp[j] --------
    if (tid < 2 * CC) {
        const int lc = 2 * (int)rank + tid / CC;   // this CTA owns 2 cluster columns
        const int j  = tid % CC;
        float acc = bp[j];
        const float* wp = Wp + (size_t)j * HH;
        #pragma unroll 4
        for (int r = 0; r < HH; r++)
            acc = fmaf(wp[r], s.Hp[cur][lc][r >> 1][r & 1], acc);
        out[(size_t)(colBase + lc) * CC + j] = acc;
    }
}

extern "C" void kernel_launch(void* const* d_in, const int* in_sizes, int n_in,
                              void* d_out, int out_size) {
    const int*   x   = (const int*)  d_in[0];
    const float* emb = (const float*)d_in[1];
    const float* Wxg = (const float*)d_in[2];
    const float* Whg = (const float*)d_in[3];
    const float* bg  = (const float*)d_in[4];
    const float* Wxi = (const float*)d_in[5];
    const float* Whi = (const float*)d_in[6];
    const float* bi  = (const float*)d_in[7];
    const float* Wxf = (const float*)d_in[8];
    const float* Whf = (const float*)d_in[9];
    const float* bf  = (const float*)d_in[10];
    const float* Wxo = (const float*)d_in[11];
    const float* Who = (const float*)d_in[12];
    const float* bo  = (const float*)d_in[13];
    const float* Wp  = (const float*)d_in[14];
    const float* bp  = (const float*)d_in[15];
    float* out = (float*)d_out;

    cudaFuncSetAttribute(lstm_persistent_kernel,
                         cudaFuncAttributeMaxDynamicSharedMemorySize,
                         (int)sizeof(Smem));

    lstm_persistent_kernel<<<128, THREADS, sizeof(Smem)>>>(
        x, emb, Wxg, Whg, bg, Wxi, Whi, bi, Wxf, Whf, bf, Wxo, Who, bo, Wp, bp, out);
}